// round 8
// baseline (speedup 1.0000x reference)
#include <cuda_runtime.h>
#include <cuda_bf16.h>
#include <cstdint>
#include <math.h>

// ---------------------------------------------------------------------------
// QuantumLayer: three FFT-diagonal rotations = ONE real 64x64 circulant along
// the qubit axis -> bf16-split mma.sync HMMA (tensor pipe). Amplitude noise
// (threefry2x32, JAX partitionable) + per-token L2 norm + abs.
// Threefry round-adds are forced onto the FMA pipe via IMAD (opaque `one`
// multiplier) to balance the alu/fma issue pipes.
// ---------------------------------------------------------------------------

#define DTOT 4096
#define CTAS 2048          // 2 tokens per CTA

// B-fragment table, fragment-register order: [img(hi,lo)][j(8)][kk(4)][lane(32)]
__device__ uint2 d_Bfrag[2048];

// ------------------------- small helpers -----------------------------------
__device__ __forceinline__ unsigned smem_u32(const void* p) {
    unsigned a;
    asm("{ .reg .u64 t; cvta.to.shared.u64 t, %1; cvt.u32.u64 %0, t; }" : "=r"(a) : "l"(p));
    return a;
}
__device__ __forceinline__ void cp_async16(void* s, const void* g) {
    asm volatile("cp.async.ca.shared.global [%0], [%1], 16;" :: "r"(smem_u32(s)), "l"(g));
}
// pack two f32 -> bf16x2, first arg in LOW half
__device__ __forceinline__ unsigned pack_bf16x2(float lo_e, float hi_e) {
    unsigned r;
    asm("cvt.rn.bf16x2.f32 %0, %1, %2;" : "=r"(r) : "f"(hi_e), "f"(lo_e));
    return r;
}
__device__ __forceinline__ void split2(float a, float b, unsigned &hi, unsigned &lo) {
    unsigned h = pack_bf16x2(a, b);
    float ha = __uint_as_float(h << 16);
    float hb = __uint_as_float(h & 0xffff0000u);
    hi = h;
    lo = pack_bf16x2(a - ha, b - hb);
}
#define HMMA(c0,c1,c2,c3,a,b0,b1)                                              \
    asm volatile("mma.sync.aligned.m16n8k16.row.col.f32.bf16.bf16.f32 "        \
        "{%0,%1,%2,%3}, {%4,%5,%6,%7}, {%8,%9}, {%0,%1,%2,%3};"                \
        : "+f"(c0), "+f"(c1), "+f"(c2), "+f"(c3)                               \
        : "r"((a)[0]), "r"((a)[1]), "r"((a)[2]), "r"((a)[3]), "r"(b0), "r"(b1))

// ------------------------- threefry2x32 --------------------------------------
__host__ __device__ __forceinline__ unsigned rotl32(unsigned x, int r) {
#if defined(__CUDA_ARCH__)
    return __funnelshift_l(x, x, r);
#else
    return (x << r) | (x >> (32 - r));
#endif
}
// host/exact version (key derivation)
__host__ __device__ __forceinline__ void threefry2x32(
    unsigned k0, unsigned k1, unsigned c0, unsigned c1, unsigned &y0, unsigned &y1)
{
    unsigned ks2 = k0 ^ k1 ^ 0x1BD11BDAu;
    unsigned x0 = c0 + k0;
    unsigned x1 = c1 + k1;
#define TF_R(r) { x0 += x1; x1 = rotl32(x1, (r)); x1 ^= x0; }
    TF_R(13) TF_R(15) TF_R(26) TF_R(6)
    x0 += k1;  x1 += ks2 + 1u;
    TF_R(17) TF_R(29) TF_R(16) TF_R(24)
    x0 += ks2; x1 += k0 + 2u;
    TF_R(13) TF_R(15) TF_R(26) TF_R(6)
    x0 += k0;  x1 += k1 + 3u;
    TF_R(17) TF_R(29) TF_R(16) TF_R(24)
    x0 += k1;  x1 += ks2 + 4u;
    TF_R(13) TF_R(15) TF_R(26) TF_R(6)
    x0 += ks2; x1 += k0 + 5u;
#undef TF_R
    y0 = x0; y1 = x1;
}

// device version: round adds forced to IMAD (fma pipe) via opaque `one`.
// counter is (0, j) -> x0 starts at k0.
__device__ __forceinline__ unsigned threefry_bits(
    unsigned k0, unsigned k1, unsigned ks2, unsigned j, unsigned one)
{
    unsigned x0 = k0;
    unsigned x1 = j + k1;
#define ADDF(a,b) asm("mad.lo.u32 %0, %1, %2, %0;" : "+r"(a) : "r"(b), "r"(one))
#define TF_R(r) { ADDF(x0, x1); x1 = rotl32(x1, (r)); x1 ^= x0; }
    TF_R(13) TF_R(15) TF_R(26) TF_R(6)
    x0 += k1;  x1 += ks2 + 1u;
    TF_R(17) TF_R(29) TF_R(16) TF_R(24)
    x0 += ks2; x1 += k0 + 2u;
    TF_R(13) TF_R(15) TF_R(26) TF_R(6)
    x0 += k0;  x1 += k1 + 3u;
    TF_R(17) TF_R(29) TF_R(16) TF_R(24)
    x0 += k1;  x1 += ks2 + 4u;
    TF_R(13) TF_R(15) TF_R(26) TF_R(6)
    x0 += ks2; x1 += k0 + 5u;
#undef TF_R
#undef ADDF
    return x0 ^ x1;
}

__device__ __forceinline__ float erfinv_approx(float x)
{
    float w = -__logf(fmaf(-x, x, 1.0f));
    float p;
    if (w < 5.0f) {
        w = w - 2.5f;
        p = 2.81022636e-08f;
        p = fmaf(p, w, 3.43273939e-07f);
        p = fmaf(p, w, -3.5233877e-06f);
        p = fmaf(p, w, -4.39150654e-06f);
        p = fmaf(p, w, 0.00021858087f);
        p = fmaf(p, w, -0.00125372503f);
        p = fmaf(p, w, -0.00417768164f);
        p = fmaf(p, w, 0.246640727f);
        p = fmaf(p, w, 1.50140941f);
    } else {
        w = sqrtf(w) - 3.0f;
        p = -0.000200214257f;
        p = fmaf(p, w, 0.000100950558f);
        p = fmaf(p, w, 0.00134934322f);
        p = fmaf(p, w, -0.00367342844f);
        p = fmaf(p, w, 0.00573950773f);
        p = fmaf(p, w, -0.0076224613f);
        p = fmaf(p, w, 0.00943887047f);
        p = fmaf(p, w, 1.00167406f);
        p = fmaf(p, w, 2.83297682f);
    }
    return p * x;
}
__device__ __forceinline__ float noise_mult(
    unsigned ka0, unsigned ka1, unsigned ks2, unsigned j, unsigned one)
{
    unsigned bits = threefry_bits(ka0, ka1, ks2, j, one);
    // exact equivalent of jax: f=bitcast((bits>>9)|0x3f800000)-1; u=fma(f,2,lo)
    float v = (float)(bits >> 9);                       // exact I2F (23 bits)
    float u = fmaf(v, 2.3841858e-07f, -0.99999994f);    // v * 2^-22 + lo
    float z = 1.41421354f * erfinv_approx(u);
    return fmaf(z, 0.01f, 1.0f);
}

// ------------------------- setup: generator + B-fragment table -------------
__global__ void setup_kernel(const float* __restrict__ rx,
                             const float* __restrict__ ry,
                             const float* __restrict__ rz)
{
    __shared__ float c64[64], s64[64];
    __shared__ float cthx[32], cthy[32], cthz[32], sthz[32];
    __shared__ float cx[64], cy[64], cz[64], hh[64], gg[64];
    const int tid = threadIdx.x;   // 0..255
    const int m = tid;

    if (m < 64) {
        c64[m] = cospif((float)m / 32.0f);
        s64[m] = sinpif((float)m / 32.0f);
    }
    if (m < 32) {
        float sx = 0.0f, sy = 0.0f, sz = 0.0f;
        for (int j = 0; j < 16; j++) {
            sx += rx[m * 16 + j];
            sy += ry[m * 16 + j];
            sz += rz[m * 16 + j];
        }
        cthx[m] = cosf(0.5f * sx);
        cthy[m] = cosf(0.5f * sy);
        cthz[m] = cosf(0.5f * sz);
        sthz[m] = sinf(0.5f * sz);
    }
    __syncthreads();

    if (m < 64) {
        float ax = 0.0f, ay = 0.0f, az = 0.0f;
        for (int k = 0; k < 32; k++) {
            int n0 = (2 * k * m) & 63;
            int n1 = ((2 * k + 1) * m) & 63;
            float cc = c64[n0] + c64[n1];
            ax = fmaf(cthx[k], cc, ax);
            ay = fmaf(cthy[k], cc, ay);
            az = fmaf(cthz[k], cc, fmaf(sthz[k], s64[n0] - s64[n1], az));
        }
        cx[m] = ax * (1.0f / 64.0f);
        cy[m] = ay * (1.0f / 64.0f);
        cz[m] = az * (1.0f / 64.0f);
    }
    __syncthreads();

    if (m < 64) {
        float acc = 0.0f;
        for (int s = 0; s < 64; s++) acc = fmaf(cy[s], cx[(m - s) & 63], acc);
        hh[m] = acc;
    }
    __syncthreads();

    if (m < 64) {
        float g = 0.0f;
        for (int s = 0; s < 64; s++) g = fmaf(cz[s], hh[(m - s) & 63], g);
        gg[m] = g;
    }
    __syncthreads();

    // B = G^T fragments for mma.m16n8k16.row.col: B[k=p][n=q] = g[(q-p)&63]
    for (int e = tid; e < 2048; e += 256) {
        int lane = e & 31;
        int kk   = (e >> 5) & 3;
        int j    = (e >> 7) & 7;
        int img  = e >> 10;
        int p0 = kk * 16 + (lane & 3) * 2;
        int q  = j * 8 + (lane >> 2);
        float v0 = gg[(q - p0) & 63];
        float v1 = gg[(q - p0 - 1) & 63];
        float v2 = gg[(q - p0 - 8) & 63];
        float v3 = gg[(q - p0 - 9) & 63];
        unsigned h0, l0, h1, l1;
        split2(v0, v1, h0, l0);
        split2(v2, v3, h1, l1);
        d_Bfrag[e] = (img == 0) ? make_uint2(h0, h1) : make_uint2(l0, l1);
    }
}

// ------------------------- main kernel -------------------------------------
__global__ void __launch_bounds__(256, 4)
quantum_main(const float* __restrict__ x, float* __restrict__ out,
             unsigned ka0, unsigned ka1, unsigned one)
{
    __shared__ __align__(16) uint2 Bf[2048];   // [img][j][kk][lane], 16KB
    __shared__ float red[8];

    const int tid = threadIdx.x;
    const int w   = tid >> 5;
    const int l   = tid & 31;
    const int t   = w >> 2;                   // token within CTA pair
    const int dg  = (w & 3) * 16 + (l >> 2);  // this thread's base d (row)
    const int blk = blockIdx.x;
    const unsigned ks2 = ka0 ^ ka1 ^ 0x1BD11BDAu;

    // --- async copy of B fragments (64B per thread) ---
#pragma unroll
    for (int i = 0; i < 4; i++)
        cp_async16(&Bf[tid * 8 + i * 2], &d_Bfrag[tid * 8 + i * 2]);
    asm volatile("cp.async.commit_group;");

    // --- A fragments straight from gmem (each byte read once, 4-sector LDGs) ---
    const float* xb = x + (size_t)(2 * blk + t) * DTOT + dg;
    unsigned ahi[4][4], alo[4][4];
#pragma unroll
    for (int kk = 0; kk < 4; kk++) {
        const float* xp = xb + (kk * 16 + (l & 3) * 2) * 64;
        float v00 = xp[0],        v01 = xp[64];
        float v10 = xp[8],        v11 = xp[64 + 8];
        float v20 = xp[512],      v21 = xp[576];
        float v30 = xp[512 + 8],  v31 = xp[576 + 8];
        split2(v00, v01, ahi[kk][0], alo[kk][0]);
        split2(v10, v11, ahi[kk][1], alo[kk][1]);
        split2(v20, v21, ahi[kk][2], alo[kk][2]);
        split2(v30, v31, ahi[kk][3], alo[kk][3]);
    }

    asm volatile("cp.async.wait_group 0;");
    __syncthreads();

    // --- 8 n-tiles: 12 HMMAs (3-term bf16 split); noisy values -> L2 (stcg) ---
    float s = 0.0f;
    const unsigned jb = (unsigned)((2 * blk + t) * DTOT) + (unsigned)dg;
    float* o = out + (size_t)(2 * blk + t) * DTOT + dg;
#pragma unroll
    for (int j = 0; j < 8; j++) {
        float c0 = 0.f, c1 = 0.f, c2 = 0.f, c3 = 0.f;
#pragma unroll
        for (int kk = 0; kk < 4; kk++) {
            uint2 bh = Bf[(j * 4 + kk) * 32 + l];
            uint2 bl = Bf[1024 + (j * 4 + kk) * 32 + l];
            HMMA(c0, c1, c2, c3, ahi[kk], bh.x, bh.y);
            HMMA(c0, c1, c2, c3, alo[kk], bh.x, bh.y);
            HMMA(c0, c1, c2, c3, ahi[kk], bl.x, bl.y);
        }
        const unsigned qe = (unsigned)(j * 8 + (l & 3) * 2);
        float n0 = noise_mult(ka0, ka1, ks2, jb + qe * 64u,       one);
        float n1 = noise_mult(ka0, ka1, ks2, jb + qe * 64u + 64u, one);
        float n2 = noise_mult(ka0, ka1, ks2, jb + qe * 64u + 8u,  one);
        float n3 = noise_mult(ka0, ka1, ks2, jb + qe * 64u + 72u, one);
        float w0 = c0 * n0, w1 = c1 * n1, w2 = c2 * n2, w3 = c3 * n3;
        s = fmaf(w0, w0, fmaf(w1, w1, fmaf(w2, w2, fmaf(w3, w3, s))));
        float* oj = o + qe * 64;
        __stcg(oj,      w0);
        __stcg(oj + 64, w1);
        __stcg(oj + 8,  w2);
        __stcg(oj + 72, w3);
    }

    // --- per-token norm: warp reduce + 4 warps per token via smem ---
#pragma unroll
    for (int off = 16; off > 0; off >>= 1)
        s += __shfl_xor_sync(0xffffffffu, s, off);
    if (l == 0) red[w] = s;
    __syncthreads();
    const float S = red[t * 4] + red[t * 4 + 1] + red[t * 4 + 2] + red[t * 4 + 3];
    const float inv = __fdividef(1.0f, sqrtf(S) + 1e-8f);

    // --- read back own values from L2, finalize |w| * inv ---
#pragma unroll
    for (int j = 0; j < 8; j++) {
        const int qe = j * 8 + (l & 3) * 2;
        float* oj = o + qe * 64;
        float w0 = __ldcg(oj);
        float w1 = __ldcg(oj + 64);
        float w2 = __ldcg(oj + 8);
        float w3 = __ldcg(oj + 72);
        __stcg(oj,      fabsf(w0) * inv);
        __stcg(oj + 64, fabsf(w1) * inv);
        __stcg(oj + 8,  fabsf(w2) * inv);
        __stcg(oj + 72, fabsf(w3) * inv);
    }
}

// ------------------------- launch ------------------------------------------
extern "C" void kernel_launch(void* const* d_in, const int* in_sizes, int n_in,
                              void* d_out, int out_size)
{
    const float* x  = (const float*)d_in[0];
    const float* rx = (const float*)d_in[1];
    const float* ry = (const float*)d_in[2];
    const float* rz = (const float*)d_in[3];
    float* out = (float*)d_out;

    unsigned ka0, ka1;
    threefry2x32(0u, 42u, 0u, 0u, ka0, ka1);

    setup_kernel<<<1, 256>>>(rx, ry, rz);
    quantum_main<<<CTAS, 256>>>(x, out, ka0, ka1, 1u /* opaque to ptxas */);
}